// round 3
// baseline (speedup 1.0000x reference)
#include <cuda_runtime.h>
#include <cuda_bf16.h>
#include <cstdint>

// DIN forward, one CTA per batch row.
// Algebra: att_in@W1 = h@(Wa+Wc) + (h*t)@Wd + t@(Wb-Wc)
//   -> per-batch weight Wb[e,j] = Wa[e,j]+Wc[e,j]+t[e]*Wd[e,j]  (K=64 GEMM)
//   -> per-batch bias  tvec[j]  = b1[j] + sum_e t[e]*(Wb_blk[e,j]-Wc[e,j])
// Mainloop uses fma.rn.f32x2 (packed dual fp32 FMA) with A stored duplicated {h,h}.

#define BATCH 4096
#define SEQ   200
#define EMB   64
#define HID   256
#define NT    256

// ---- smem layout (in floats) ----
#define OFF_HD    0                      // duplicated h: [200][64] float2 = 25600 f
#define OFF_WB    (OFF_HD + 25600)       // Wb: [64][256] = 16384 f
#define OFF_TVEC  (OFF_WB + 16384)       // 256
#define OFF_TVAL  (OFF_TVEC + 256)       // 64
#define OFF_W2    (OFF_TVAL + 64)        // 256 (attn_w2)
#define OFF_WLOG  (OFF_W2 + 256)         // 2*200 = 400
#define OFF_LOGW  (OFF_WLOG + 400)       // 200 (softmax weights)
#define OFF_UIP   (OFF_LOGW + 200)       // 4*64 = 256
#define OFF_UI    (OFF_UIP + 256)        // 64
#define OFF_RED   (OFF_UI + 64)          // 32
#define OFF_HIST  (OFF_RED + 32)         // 200 (ints stored in float slots)
#define SMEM_F    (OFF_HIST + 200)       // 43712 floats
#define SMEM_BYTES (SMEM_F * 4)          // 174848 bytes

__device__ __forceinline__ void fma2(unsigned long long &d,
                                     unsigned long long a,
                                     unsigned long long b) {
    asm("fma.rn.f32x2 %0, %1, %2, %0;" : "+l"(d) : "l"(a), "l"(b));
}
__device__ __forceinline__ unsigned long long pk2(float x, float y) {
    unsigned long long r;
    asm("mov.b64 %0, {%1, %2};" : "=l"(r) : "f"(x), "f"(y));
    return r;
}
__device__ __forceinline__ float2 upk2(unsigned long long v) {
    float2 r;
    asm("mov.b64 {%0, %1}, %2;" : "=f"(r.x), "=f"(r.y) : "l"(v));
    return r;
}

__device__ __forceinline__ float block_reduce_sum(float v, float* red, int tid) {
    #pragma unroll
    for (int o = 16; o; o >>= 1) v += __shfl_xor_sync(0xffffffffu, v, o);
    if ((tid & 31) == 0) red[tid >> 5] = v;
    __syncthreads();
    if (tid < 32) {
        float r = (tid < 8) ? red[tid] : 0.0f;
        #pragma unroll
        for (int o = 4; o; o >>= 1) r += __shfl_xor_sync(0xffffffffu, r, o);
        if (tid == 0) red[0] = r;
    }
    __syncthreads();
    float out = red[0];
    __syncthreads();
    return out;
}

__device__ __forceinline__ float block_reduce_max(float v, float* red, int tid) {
    #pragma unroll
    for (int o = 16; o; o >>= 1) v = fmaxf(v, __shfl_xor_sync(0xffffffffu, v, o));
    if ((tid & 31) == 0) red[tid >> 5] = v;
    __syncthreads();
    if (tid < 32) {
        float r = (tid < 8) ? red[tid] : -3.4e38f;
        #pragma unroll
        for (int o = 4; o; o >>= 1) r = fmaxf(r, __shfl_xor_sync(0xffffffffu, r, o));
        if (tid == 0) red[0] = r;
    }
    __syncthreads();
    float out = red[0];
    __syncthreads();
    return out;
}

__global__ __launch_bounds__(NT, 1)
void din_kernel(const int*   __restrict__ user_hist,    // [B, S]
                const int*   __restrict__ target_item,  // [B]
                const float* __restrict__ user_emb,     // [V, 64]
                const float* __restrict__ item_emb,     // [V, 64]
                const float* __restrict__ attn_w1,      // [256, 256]
                const float* __restrict__ attn_b1,      // [256]
                const float* __restrict__ attn_w2,      // [256]
                const float* __restrict__ mlp_w1,       // [128, 256]
                const float* __restrict__ mlp_b1,       // [256]
                const float* __restrict__ mlp_w2,       // [256]
                const float* __restrict__ mlp_b2,       // [1]
                float* __restrict__ out)                // [B]
{
    extern __shared__ float sh[];
    const int tid = threadIdx.x;
    const int b   = blockIdx.x;

    int*   shist = (int*)(sh + OFF_HIST);
    float* tvalS = sh + OFF_TVAL;
    float* w2S   = sh + OFF_W2;
    float* tvecS = sh + OFF_TVEC;
    float* wbS   = sh + OFF_WB;
    float* wlogS = sh + OFF_WLOG;
    float* logwS = sh + OFF_LOGW;
    float* uipS  = sh + OFF_UIP;
    float* uiS   = sh + OFF_UI;
    float* redS  = sh + OFF_RED;

    // ---- phase 0: small loads ----
    if (tid < SEQ) shist[tid] = user_hist[b * SEQ + tid];
    if (tid < EMB) {
        int tgt = target_item[b];
        tvalS[tid] = item_emb[tgt * EMB + tid];
    }
    w2S[tid] = attn_w2[tid];
    __syncthreads();

    // ---- phase 1: gather h into duplicated-{h,h} smem ----
    {
        const float4* ue4 = (const float4*)user_emb;
        float4* hd4 = (float4*)(sh + OFF_HD);
        for (int u = tid; u < SEQ * 16; u += NT) {
            int s = u >> 4, q = u & 15;
            float4 v = ue4[shist[s] * 16 + q];
            int base = s * 32 + q * 2;   // float4 index into duplicated row (32 float4 per row)
            hd4[base]     = make_float4(v.x, v.x, v.y, v.y);
            hd4[base + 1] = make_float4(v.z, v.z, v.w, v.w);
        }
    }

    // ---- phase 2: build per-batch Wb and tvec ----
    {
        const int j = tid;
        float accT = attn_b1[j];
        #pragma unroll 4
        for (int e = 0; e < EMB; ++e) {
            float te = tvalS[e];
            float a0 = attn_w1[e * HID + j];            // Wa (h)
            float a1 = attn_w1[(64 + e) * HID + j];     // Wb_blk (t)
            float a2 = attn_w1[(128 + e) * HID + j];    // Wc (h - t)
            float a3 = attn_w1[(192 + e) * HID + j];    // Wd (h * t)
            wbS[e * HID + j] = a0 + a2 + te * a3;
            accT += te * (a1 - a2);
        }
        tvecS[j] = accT;
    }
    __syncthreads();

    // ---- phase 3: [200,64]@[64,256] GEMM with f32x2, fused relu·w2 reduce ----
    {
        const unsigned long long* hdq = (const unsigned long long*)(sh + OFF_HD);
        const unsigned long long* wbq = (const unsigned long long*)wbS;
        const int tx   = tid & 63;   // 64 col-groups of 4
        const int ty   = tid >> 6;   // 4 row-groups of 10
        const int lane = tid & 31;
        const int warp = tid >> 5;

        float4 tv  = *(const float4*)&tvecS[tx * 4];
        float4 w2v = *(const float4*)&w2S[tx * 4];
        unsigned long long t01 = pk2(tv.x, tv.y);
        unsigned long long t23 = pk2(tv.z, tv.w);

        for (int it = 0; it < 5; ++it) {
            const int r0 = it * 40 + ty * 10;
            unsigned long long accA[10], accB[10];
            #pragma unroll
            for (int i = 0; i < 10; ++i) { accA[i] = t01; accB[i] = t23; }

            #pragma unroll 2
            for (int k = 0; k < EMB; ++k) {
                unsigned long long b0 = wbq[k * 128 + tx * 2];
                unsigned long long b1 = wbq[k * 128 + tx * 2 + 1];
                #pragma unroll
                for (int i = 0; i < 10; ++i) {
                    unsigned long long a = hdq[(r0 + i) * EMB + k];
                    fma2(accA[i], a, b0);
                    fma2(accB[i], a, b1);
                }
            }

            #pragma unroll
            for (int i = 0; i < 10; ++i) {
                float2 pa = upk2(accA[i]);
                float2 pb = upk2(accB[i]);
                float p = fmaxf(pa.x, 0.0f) * w2v.x + fmaxf(pa.y, 0.0f) * w2v.y
                        + fmaxf(pb.x, 0.0f) * w2v.z + fmaxf(pb.y, 0.0f) * w2v.w;
                #pragma unroll
                for (int o = 16; o; o >>= 1) p += __shfl_xor_sync(0xffffffffu, p, o);
                if (lane == 0) wlogS[(warp & 1) * SEQ + r0 + i] = p;
            }
        }
    }
    __syncthreads();

    // ---- phase 4: softmax over S ----
    {
        float l = -3.4e38f;
        if (tid < SEQ) l = wlogS[tid] + wlogS[SEQ + tid];
        float mx = block_reduce_max(l, redS, tid);
        float ex = (tid < SEQ) ? __expf(l - mx) : 0.0f;
        float sm = block_reduce_sum(ex, redS, tid);
        if (tid < SEQ) logwS[tid] = ex / sm;
    }
    __syncthreads();

    // ---- phase 5: user_interest = sum_s w[s] * h[s,:] ----
    {
        const float* hdf = sh + OFF_HD;  // duplicated; read .x half
        int e = tid & 63, part = tid >> 6;
        float acc = 0.0f;
        int s0 = part * 50;
        #pragma unroll 5
        for (int s = s0; s < s0 + 50; ++s)
            acc += logwS[s] * hdf[(s * EMB + e) * 2];
        uipS[part * 64 + e] = acc;
    }
    __syncthreads();
    if (tid < EMB)
        uiS[tid] = uipS[tid] + uipS[64 + tid] + uipS[128 + tid] + uipS[192 + tid];
    __syncthreads();

    // ---- phase 6: prediction MLP + sigmoid ----
    {
        const int j = tid;
        float acc = mlp_b1[j];
        #pragma unroll 4
        for (int k = 0; k < EMB; ++k)
            acc += uiS[k] * mlp_w1[k * HID + j];
        #pragma unroll 4
        for (int k = 0; k < EMB; ++k)
            acc += tvalS[k] * mlp_w1[(64 + k) * HID + j];
        float p = fmaxf(acc, 0.0f) * mlp_w2[j];
        float s2 = block_reduce_sum(p, redS, tid);
        if (tid == 0)
            out[b] = 1.0f / (1.0f + __expf(-(s2 + mlp_b2[0])));
    }
}

extern "C" void kernel_launch(void* const* d_in, const int* in_sizes, int n_in,
                              void* d_out, int out_size) {
    const int*   user_hist   = (const int*)  d_in[0];
    const int*   target_item = (const int*)  d_in[1];
    const float* user_emb    = (const float*)d_in[2];
    const float* item_emb    = (const float*)d_in[3];
    const float* attn_w1     = (const float*)d_in[4];
    const float* attn_b1     = (const float*)d_in[5];
    const float* attn_w2     = (const float*)d_in[6];
    // d_in[7] = attn_b2 (constant shift inside softmax -> no effect, skipped)
    const float* mlp_w1      = (const float*)d_in[8];
    const float* mlp_b1      = (const float*)d_in[9];
    const float* mlp_w2      = (const float*)d_in[10];
    const float* mlp_b2      = (const float*)d_in[11];
    float* out = (float*)d_out;

    cudaFuncSetAttribute(din_kernel,
                         cudaFuncAttributeMaxDynamicSharedMemorySize, SMEM_BYTES);
    din_kernel<<<BATCH, NT, SMEM_BYTES>>>(
        user_hist, target_item, user_emb, item_emb,
        attn_w1, attn_b1, attn_w2,
        mlp_w1, mlp_b1, mlp_w2, mlp_b2, out);
}

// round 5
// speedup vs baseline: 1.7508x; 1.7508x over previous
#include <cuda_runtime.h>
#include <cuda_bf16.h>
#include <cstdint>

// DIN forward, one CTA per batch row, 2 CTAs/SM.
// Algebra: att_in@W1 = h@(Wa+Wc) + (h*t)@Wd + t@(Wb-Wc)
//   -> per-batch weight Wb[e,j] = Wa[e,j]+Wc[e,j]+t[e]*Wd[e,j]  (K=64 GEMM)
//   -> per-batch bias  tvec[j]  = b1[j] + sum_e t[e]*(Wb_blk[e,j]-Wc[e,j])
// Mainloop: fma.rn.f32x2, A packed over ROW PAIRS {h[2p][k],h[2p+1][k]},
// B duplicated per-column in registers. S processed in halves {120,80} so
// SMEM fits 2 CTAs/SM.

#define BATCH 4096
#define SEQ   200
#define EMB   64
#define HID   256
#define NT    256
#define RSTR  65   // f32x2 stride per k-row of hp (60 pairs + pad, odd -> 4-way scatter)

typedef unsigned long long ull;

// ---- smem layout (in floats) ----
#define OFF_HP    0                       // hp: [64][RSTR] f32x2 = 64*130 = 8320 f
#define OFF_WB    (OFF_HP + 64*2*RSTR)    // Wb: [64][256] = 16384 f
#define OFF_TVEC  (OFF_WB + 16384)        // 256
#define OFF_TVAL  (OFF_TVEC + 256)        // 64
#define OFF_W2    (OFF_TVAL + 64)         // 256
#define OFF_WLOG  (OFF_W2 + 256)          // 2*200 = 400
#define OFF_LOGW  (OFF_WLOG + 400)        // 200
#define OFF_UIP   (OFF_LOGW + 200)        // 256
#define OFF_UI    (OFF_UIP + 256)         // 64
#define OFF_RED   (OFF_UI + 64)           // 32
#define OFF_HIST  (OFF_RED + 32)          // 200
#define SMEM_F    (OFF_HIST + 200)
#define SMEM_BYTES (SMEM_F * 4)           // 105,728 bytes -> 2 CTAs/SM

__device__ __forceinline__ void fma2(ull &d, ull a, ull b) {
    asm("fma.rn.f32x2 %0, %1, %2, %0;" : "+l"(d) : "l"(a), "l"(b));
}
__device__ __forceinline__ ull pk2(float x, float y) {
    ull r;
    asm("mov.b64 %0, {%1, %2};" : "=l"(r) : "f"(x), "f"(y));
    return r;
}
__device__ __forceinline__ float2 upk2(ull v) {
    float2 r;
    asm("mov.b64 {%0, %1}, %2;" : "=f"(r.x), "=f"(r.y) : "l"(v));
    return r;
}

__device__ __forceinline__ float block_reduce_sum(float v, float* red, int tid) {
    #pragma unroll
    for (int o = 16; o; o >>= 1) v += __shfl_xor_sync(0xffffffffu, v, o);
    if ((tid & 31) == 0) red[tid >> 5] = v;
    __syncthreads();
    if (tid < 32) {
        float r = (tid < 8) ? red[tid] : 0.0f;
        #pragma unroll
        for (int o = 4; o; o >>= 1) r += __shfl_xor_sync(0xffffffffu, r, o);
        if (tid == 0) red[0] = r;
    }
    __syncthreads();
    float out = red[0];
    __syncthreads();
    return out;
}

__device__ __forceinline__ float block_reduce_max(float v, float* red, int tid) {
    #pragma unroll
    for (int o = 16; o; o >>= 1) v = fmaxf(v, __shfl_xor_sync(0xffffffffu, v, o));
    if ((tid & 31) == 0) red[tid >> 5] = v;
    __syncthreads();
    if (tid < 32) {
        float r = (tid < 8) ? red[tid] : -3.4e38f;
        #pragma unroll
        for (int o = 4; o; o >>= 1) r = fmaxf(r, __shfl_xor_sync(0xffffffffu, r, o));
        if (tid == 0) red[0] = r;
    }
    __syncthreads();
    float out = red[0];
    __syncthreads();
    return out;
}

__global__ __launch_bounds__(NT, 2)
void din_kernel(const int*   __restrict__ user_hist,    // [B, S]
                const int*   __restrict__ target_item,  // [B]
                const float* __restrict__ user_emb,     // [V, 64]
                const float* __restrict__ item_emb,     // [V, 64]
                const float* __restrict__ attn_w1,      // [256, 256]
                const float* __restrict__ attn_b1,      // [256]
                const float* __restrict__ attn_w2,      // [256]
                const float* __restrict__ mlp_w1,       // [128, 256]
                const float* __restrict__ mlp_b1,       // [256]
                const float* __restrict__ mlp_w2,       // [256]
                const float* __restrict__ mlp_b2,       // [1]
                float* __restrict__ out)                // [B]
{
    extern __shared__ float sh[];
    const int tid = threadIdx.x;
    const int b   = blockIdx.x;

    int*   shist = (int*)(sh + OFF_HIST);
    float* tvalS = sh + OFF_TVAL;
    float* w2S   = sh + OFF_W2;
    float* tvecS = sh + OFF_TVEC;
    float* wbS   = sh + OFF_WB;
    float* wlogS = sh + OFF_WLOG;
    float* logwS = sh + OFF_LOGW;
    float* uipS  = sh + OFF_UIP;
    float* uiS   = sh + OFF_UI;
    float* redS  = sh + OFF_RED;

    // ---- phase 0: small loads ----
    if (tid < SEQ) shist[tid] = user_hist[b * SEQ + tid];
    if (tid < EMB) {
        int tgt = target_item[b];
        tvalS[tid] = item_emb[tgt * EMB + tid];
    }
    w2S[tid] = attn_w2[tid];
    __syncthreads();

    // ---- phase 2: build per-batch Wb and tvec ----
    {
        const int j = tid;
        float accT = attn_b1[j];
        #pragma unroll 4
        for (int e = 0; e < EMB; ++e) {
            float te = tvalS[e];
            float a0 = attn_w1[e * HID + j];            // Wa (h)
            float a1 = attn_w1[(64 + e) * HID + j];     // Wb_blk (t)
            float a2 = attn_w1[(128 + e) * HID + j];    // Wc (h - t)
            float a3 = attn_w1[(192 + e) * HID + j];    // Wd (h * t)
            wbS[e * HID + j] = a0 + a2 + te * a3;
            accT += te * (a1 - a2);
        }
        tvecS[j] = accT;
    }

    // ---- phase 3: logits over S in two halves {120, 80} ----
    const int tx   = tid & 63;   // 64 col-groups of 4
    const int ty   = tid >> 6;   // 4 pair-groups
    const int lane = tid & 31;
    const int warp = tid >> 5;

    __syncthreads();             // Wb + hist ready

    float4 tv  = *(const float4*)&tvecS[tx * 4];
    float4 w2v = *(const float4*)&w2S[tx * 4];
    float w2a[4] = {w2v.x, w2v.y, w2v.z, w2v.w};
    ull tdup[4] = {pk2(tv.x, tv.x), pk2(tv.y, tv.y), pk2(tv.z, tv.z), pk2(tv.w, tv.w)};

    for (int half = 0; half < 2; ++half) {
        const int s0  = half * 120;
        const int len = half ? 80 : 120;

        // gather h rows [s0, s0+len) into pair-packed hp (transposed)
        {
            const float4* ue4 = (const float4*)user_emb;
            for (int u = tid; u < len * 16; u += NT) {
                int sl = u >> 4, q = u & 15;
                float4 v = ue4[(size_t)shist[s0 + sl] * 16 + q];
                float* base = sh + OFF_HP + (sl & 1) + 2 * (sl >> 1);
                int e0 = q * 4;
                base[(e0 + 0) * (2 * RSTR)] = v.x;
                base[(e0 + 1) * (2 * RSTR)] = v.y;
                base[(e0 + 2) * (2 * RSTR)] = v.z;
                base[(e0 + 3) * (2 * RSTR)] = v.w;
            }
        }
        __syncthreads();

        const ull* hpq = (const ull*)(sh + OFF_HP);
        const float4* wb4 = (const float4*)wbS;
        const int nIter = half ? 2 : 3;

        for (int it = 0; it < nIter; ++it) {
            const int p0 = it * 20 + ty * 5;
            ull acc[5][4];
            #pragma unroll
            for (int i = 0; i < 5; ++i) {
                acc[i][0] = tdup[0]; acc[i][1] = tdup[1];
                acc[i][2] = tdup[2]; acc[i][3] = tdup[3];
            }

            #pragma unroll 4
            for (int k = 0; k < EMB; ++k) {
                float4 w = wb4[k * 64 + tx];
                ull b0 = pk2(w.x, w.x), b1 = pk2(w.y, w.y);
                ull b2 = pk2(w.z, w.z), b3 = pk2(w.w, w.w);
                ull a[5];
                #pragma unroll
                for (int i = 0; i < 5; ++i) a[i] = hpq[k * RSTR + p0 + i];
                #pragma unroll
                for (int i = 0; i < 5; ++i) {
                    fma2(acc[i][0], a[i], b0);
                    fma2(acc[i][1], a[i], b1);
                    fma2(acc[i][2], a[i], b2);
                    fma2(acc[i][3], a[i], b3);
                }
            }

            // epilogue: relu * w2, reduce over this warp's 32 col-groups
            #pragma unroll
            for (int i = 0; i < 5; ++i) {
                float se = 0.0f, so = 0.0f;
                #pragma unroll
                for (int c = 0; c < 4; ++c) {
                    float2 v = upk2(acc[i][c]);
                    se += fmaxf(v.x, 0.0f) * w2a[c];
                    so += fmaxf(v.y, 0.0f) * w2a[c];
                }
                #pragma unroll
                for (int o = 16; o; o >>= 1) {
                    se += __shfl_xor_sync(0xffffffffu, se, o);
                    so += __shfl_xor_sync(0xffffffffu, so, o);
                }
                if (lane == 0) {
                    int r = s0 + 2 * (p0 + i);
                    wlogS[(warp & 1) * SEQ + r]     = se;
                    wlogS[(warp & 1) * SEQ + r + 1] = so;
                }
            }
        }
        __syncthreads();   // wlog written; hp free to overwrite next half
    }

    // ---- phase 4: softmax over S ----
    {
        float l = -3.4e38f;
        if (tid < SEQ) l = wlogS[tid] + wlogS[SEQ + tid];
        float mx = block_reduce_max(l, redS, tid);
        float ex = (tid < SEQ) ? __expf(l - mx) : 0.0f;
        float sm = block_reduce_sum(ex, redS, tid);
        if (tid < SEQ) logwS[tid] = ex / sm;
    }
    __syncthreads();

    // ---- phase 5: user_interest = sum_s w[s] * h[s,:] (re-gather from L2) ----
    {
        int e = tid & 63, part = tid >> 6;
        float acc = 0.0f;
        int sA = part * 50;
        #pragma unroll 5
        for (int s = sA; s < sA + 50; ++s)
            acc += logwS[s] * __ldg(&user_emb[(size_t)shist[s] * EMB + e]);
        uipS[part * 64 + e] = acc;
    }
    __syncthreads();
    if (tid < EMB)
        uiS[tid] = uipS[tid] + uipS[64 + tid] + uipS[128 + tid] + uipS[192 + tid];
    __syncthreads();

    // ---- phase 6: prediction MLP + sigmoid ----
    {
        const int j = tid;
        float acc = mlp_b1[j];
        #pragma unroll 4
        for (int k = 0; k < EMB; ++k)
            acc += uiS[k] * mlp_w1[k * HID + j];
        #pragma unroll 4
        for (int k = 0; k < EMB; ++k)
            acc += tvalS[k] * mlp_w1[(64 + k) * HID + j];
        float p = fmaxf(acc, 0.0f) * mlp_w2[j];
        float s2 = block_reduce_sum(p, redS, tid);
        if (tid == 0)
            out[b] = 1.0f / (1.0f + __expf(-(s2 + mlp_b2[0])));
    }
}

extern "C" void kernel_launch(void* const* d_in, const int* in_sizes, int n_in,
                              void* d_out, int out_size) {
    const int*   user_hist   = (const int*)  d_in[0];
    const int*   target_item = (const int*)  d_in[1];
    const float* user_emb    = (const float*)d_in[2];
    const float* item_emb    = (const float*)d_in[3];
    const float* attn_w1     = (const float*)d_in[4];
    const float* attn_b1     = (const float*)d_in[5];
    const float* attn_w2     = (const float*)d_in[6];
    // d_in[7] = attn_b2 (constant shift inside softmax -> no effect)
    const float* mlp_w1      = (const float*)d_in[8];
    const float* mlp_b1      = (const float*)d_in[9];
    const float* mlp_w2      = (const float*)d_in[10];
    const float* mlp_b2      = (const float*)d_in[11];
    float* out = (float*)d_out;

    cudaFuncSetAttribute(din_kernel,
                         cudaFuncAttributeMaxDynamicSharedMemorySize, SMEM_BYTES);
    din_kernel<<<BATCH, NT, SMEM_BYTES>>>(
        user_hist, target_item, user_emb, item_emb,
        attn_w1, attn_b1, attn_w2,
        mlp_w1, mlp_b1, mlp_w2, mlp_b2, out);
}

// round 10
// speedup vs baseline: 5.1500x; 2.9416x over previous
#include <cuda_runtime.h>
#include <cuda_bf16.h>
#include <cstdint>

// DIN forward via mma.sync bf16 tensor cores (compute_103-safe; no tcgen05).
// Algebra: att_in@W1 = h@Wb + bias,  Wb = (Wa+Wc) + t.*Wd  (per-batch, K=64),
//          bias tvec[j] = b1[j] + sum_e t[e]*(Wb_blk-Wc)[e][j].
// prep_kernel packs static bf16 mats: g_wacd = {Wa+Wc, Wd}, g_diff = Wb_blk-Wc.
// din_kernel (1 CTA/batch, 3 CTAs/SM): build A=h bf16 [208x64] + B=Wb bf16
// [256n x 64k] in SMEM, 13x32x4 mma.m16n8k16, epilogue fuses relu(.+tvec)*w2
// into logits, softmax, user_interest from bf16 A tile. head_kernel: MLP.

#define BATCH 4096
#define SEQ   200
#define EMB   64
#define HID   256
#define NT    256

#define ASTR       72            // bf16 elems per row (64 + 8 pad)
#define ROWB       144           // bytes per row
#define MTILES     13
#define AROWS      208

typedef unsigned long long ull;

// ---- smem layout (bytes) ----
#define OFF_A      0
#define A_BYTES    (AROWS * ROWB)            // 29952
#define OFF_B      A_BYTES                   // [256 n][72 k] bf16
#define B_BYTES    (256 * ROWB)              // 36864
#define OFF_MISC   (OFF_B + B_BYTES)         // 66816
#define MO_HIST    0                         // int[200]
#define MO_TVAL    800                       // float[64]
#define MO_TW      1056                      // float2[256] {tvec, w2}
#define MO_LOGIT   3104                      // float[208]
#define MO_LOGW    3936                      // float[200] (pad to 800)
#define MO_RED     4736                      // float[32]
#define MO_UIP     4864                      // float[256]
#define MISC_BYTES 5888
#define SMEM_BYTES (OFF_MISC + MISC_BYTES)   // 72704 -> 3 CTAs/SM

__device__ __nv_bfloat162 g_wacd[EMB * HID]; // {Wa+Wc, Wd}
__device__ __nv_bfloat16  g_diff[EMB * HID]; // Wb_blk - Wc
__device__ float g_ui[BATCH * EMB];
__device__ float g_tv[BATCH * EMB];

__device__ __forceinline__ uint32_t smem_to_u32(const void* p) {
    uint32_t a;
    asm("{ .reg .u64 t; cvta.to.shared.u64 t, %1; cvt.u32.u64 %0, t; }"
        : "=r"(a) : "l"(p));
    return a;
}
__device__ __forceinline__ ull pack4bf(float a, float b, float c, float d) {
    __nv_bfloat162 lo = __floats2bfloat162_rn(a, b);
    __nv_bfloat162 hi = __floats2bfloat162_rn(c, d);
    uint32_t l32 = *(uint32_t*)&lo, h32 = *(uint32_t*)&hi;
    ull r;
    asm("mov.b64 %0, {%1, %2};" : "=l"(r) : "r"(l32), "r"(h32));
    return r;
}

#define LDSM_X4(r0, r1, r2, r3, addr) \
    asm volatile("ldmatrix.sync.aligned.m8n8.x4.shared.b16 {%0,%1,%2,%3}, [%4];" \
                 : "=r"(r0), "=r"(r1), "=r"(r2), "=r"(r3) : "r"(addr))
#define LDSM_X2(r0, r1, addr) \
    asm volatile("ldmatrix.sync.aligned.m8n8.x2.shared.b16 {%0,%1}, [%2];" \
                 : "=r"(r0), "=r"(r1) : "r"(addr))
#define MMA16816(c0, c1, c2, c3, a0, a1, a2, a3, b0, b1) \
    asm volatile("mma.sync.aligned.m16n8k16.row.col.f32.bf16.bf16.f32 " \
                 "{%0,%1,%2,%3}, {%4,%5,%6,%7}, {%8,%9}, {%0,%1,%2,%3};" \
                 : "+f"(c0), "+f"(c1), "+f"(c2), "+f"(c3) \
                 : "r"(a0), "r"(a1), "r"(a2), "r"(a3), "r"(b0), "r"(b1))

__device__ __forceinline__ float block_reduce_sum(float v, float* red, int tid) {
    #pragma unroll
    for (int o = 16; o; o >>= 1) v += __shfl_xor_sync(0xffffffffu, v, o);
    if ((tid & 31) == 0) red[tid >> 5] = v;
    __syncthreads();
    if (tid < 32) {
        float r = (tid < 8) ? red[tid] : 0.0f;
        #pragma unroll
        for (int o = 4; o; o >>= 1) r += __shfl_xor_sync(0xffffffffu, r, o);
        if (tid == 0) red[0] = r;
    }
    __syncthreads();
    float out = red[0];
    __syncthreads();
    return out;
}
__device__ __forceinline__ float block_reduce_max(float v, float* red, int tid) {
    #pragma unroll
    for (int o = 16; o; o >>= 1) v = fmaxf(v, __shfl_xor_sync(0xffffffffu, v, o));
    if ((tid & 31) == 0) red[tid >> 5] = v;
    __syncthreads();
    if (tid < 32) {
        float r = (tid < 8) ? red[tid] : -3.4e38f;
        #pragma unroll
        for (int o = 4; o; o >>= 1) r = fmaxf(r, __shfl_xor_sync(0xffffffffu, r, o));
        if (tid == 0) red[0] = r;
    }
    __syncthreads();
    float out = red[0];
    __syncthreads();
    return out;
}

// ---------------- prep: static bf16 weight packs ----------------
__global__ void prep_kernel(const float* __restrict__ w1) {
    const int j = threadIdx.x;   // 0..255
    const int e = blockIdx.x;    // 0..63
    float wa = w1[e * HID + j];
    float wb = w1[(64 + e) * HID + j];
    float wc = w1[(128 + e) * HID + j];
    float wd = w1[(192 + e) * HID + j];
    g_wacd[e * HID + j] = __floats2bfloat162_rn(wa + wc, wd);
    g_diff[e * HID + j] = __float2bfloat16(wb - wc);
}

// ---------------- main: per-batch attention ----------------
__global__ __launch_bounds__(NT, 3)
void din_kernel(const int*   __restrict__ user_hist,
                const int*   __restrict__ target_item,
                const float* __restrict__ user_emb,
                const float* __restrict__ item_emb,
                const float* __restrict__ attn_b1,
                const float* __restrict__ attn_w2)
{
    extern __shared__ char smc[];
    const uint32_t smem_base = smem_to_u32(smc);
    const int tid = threadIdx.x, b = blockIdx.x;
    const int wid = tid >> 5, lane = tid & 31;

    char* miscc   = smc + OFF_MISC;
    int*    shist = (int*)(miscc + MO_HIST);
    float*  tvalS = (float*)(miscc + MO_TVAL);
    float2* twS   = (float2*)(miscc + MO_TW);
    float* logitS = (float*)(miscc + MO_LOGIT);
    float* logwS  = (float*)(miscc + MO_LOGW);
    float* redS   = (float*)(miscc + MO_RED);
    float* uipS   = (float*)(miscc + MO_UIP);

    // ---- phase 0: hist + target embedding ----
    if (tid < SEQ) shist[tid] = user_hist[b * SEQ + tid];
    if (tid < EMB) {
        int tgt = target_item[b];
        tvalS[tid] = item_emb[(size_t)tgt * EMB + tid];
    }
    __syncthreads();

    // ---- phase 1a: A = h bf16 [208 x 64], rows 200..207 zeroed ----
    {
        const float4* ue4 = (const float4*)user_emb;
        for (int u = tid; u < SEQ * 16; u += NT) {
            int s = u >> 4, q = u & 15;
            float4 h4 = ue4[(size_t)shist[s] * 16 + q];
            *(ull*)(smc + OFF_A + s * ROWB + q * 8) = pack4bf(h4.x, h4.y, h4.z, h4.w);
        }
        #pragma unroll
        for (int i = tid; i < 8 * ROWB / 4; i += NT)
            *(uint32_t*)(smc + OFF_A + SEQ * ROWB + i * 4) = 0;
    }

    // ---- phase 1b: B = Wb bf16 [256 n][64 k] + tvec ----
    {
        const int j = tid;
        float tv_acc = attn_b1[j];
        __nv_bfloat16* Brow = (__nv_bfloat16*)(smc + OFF_B + j * ROWB);
        #pragma unroll 8
        for (int e = 0; e < EMB; e += 2) {
            __nv_bfloat162 p0 = g_wacd[e * HID + j];
            __nv_bfloat162 p1 = g_wacd[(e + 1) * HID + j];
            float t0 = tvalS[e], t1 = tvalS[e + 1];
            float v0 = __bfloat162float(p0.x) + t0 * __bfloat162float(p0.y);
            float v1 = __bfloat162float(p1.x) + t1 * __bfloat162float(p1.y);
            *(__nv_bfloat162*)(Brow + e) = __floats2bfloat162_rn(v0, v1);
            tv_acc += t0 * __bfloat162float(g_diff[e * HID + j])
                    + t1 * __bfloat162float(g_diff[(e + 1) * HID + j]);
        }
        twS[j] = make_float2(tv_acc, attn_w2[j]);
    }
    __syncthreads();

    // ---- phase 2: GEMM [208x64]@[64x256] + fused relu*w2 logit epilogue ----
    {
        const uint32_t aBase = smem_base + OFF_A
                             + (uint32_t)(lane & 15) * ROWB + (uint32_t)(lane >> 4) * 16;
        const uint32_t bBase = smem_base + OFF_B
                             + (uint32_t)(lane & 7) * ROWB + (uint32_t)((lane >> 3) & 1) * 16;
        #pragma unroll
        for (int rep = 0; rep < 2; ++rep) {
            int mt = wid + rep * 8;
            if (mt >= MTILES) break;
            uint32_t a[4][4];
            #pragma unroll
            for (int kk = 0; kk < 4; ++kk)
                LDSM_X4(a[kk][0], a[kk][1], a[kk][2], a[kk][3],
                        aBase + (uint32_t)mt * (16 * ROWB) + (uint32_t)kk * 32);
            float p0 = 0.0f, p1 = 0.0f;
            #pragma unroll 4
            for (int nt = 0; nt < 32; ++nt) {
                float c0 = 0.f, c1 = 0.f, c2 = 0.f, c3 = 0.f;
                #pragma unroll
                for (int kk = 0; kk < 4; ++kk) {
                    uint32_t b0, b1;
                    LDSM_X2(b0, b1, bBase + (uint32_t)nt * (8 * ROWB) + (uint32_t)kk * 32);
                    MMA16816(c0, c1, c2, c3,
                             a[kk][0], a[kk][1], a[kk][2], a[kk][3], b0, b1);
                }
                float4 tw = *(const float4*)(twS + (nt * 8 + (lane & 3) * 2));
                p0 += fmaxf(c0 + tw.x, 0.f) * tw.y + fmaxf(c1 + tw.z, 0.f) * tw.w;
                p1 += fmaxf(c2 + tw.x, 0.f) * tw.y + fmaxf(c3 + tw.z, 0.f) * tw.w;
            }
            p0 += __shfl_xor_sync(0xffffffffu, p0, 1);
            p0 += __shfl_xor_sync(0xffffffffu, p0, 2);
            p1 += __shfl_xor_sync(0xffffffffu, p1, 1);
            p1 += __shfl_xor_sync(0xffffffffu, p1, 2);
            if ((lane & 3) == 0) {
                int r = mt * 16 + (lane >> 2);
                logitS[r] = p0;        // rows >= SEQ land in pad slots (<208)
                logitS[r + 8] = p1;
            }
        }
    }
    __syncthreads();

    // ---- phase 3: softmax over S ----
    {
        float l = -3.4e38f;
        if (tid < SEQ) l = logitS[tid];
        float mx = block_reduce_max(l, redS, tid);
        float ex = (tid < SEQ) ? __expf(l - mx) : 0.0f;
        float sm = block_reduce_sum(ex, redS, tid);
        if (tid < SEQ) logwS[tid] = ex / sm;
    }
    __syncthreads();

    // ---- phase 4: user_interest from bf16 A tile ----
    {
        const __nv_bfloat16* Ah = (const __nv_bfloat16*)(smc + OFF_A);
        int e = tid & 63, part = tid >> 6;
        float acc = 0.0f;
        int sA = part * 50;
        #pragma unroll 10
        for (int s = sA; s < sA + 50; ++s)
            acc += logwS[s] * __bfloat162float(Ah[s * ASTR + e]);
        uipS[part * 64 + e] = acc;
    }
    __syncthreads();
    if (tid < EMB) {
        float ui = uipS[tid] + uipS[64 + tid] + uipS[128 + tid] + uipS[192 + tid];
        g_ui[b * EMB + tid] = ui;
        g_tv[b * EMB + tid] = tvalS[tid];
    }
}

// ---------------- head: prediction MLP, 16 batches per CTA ----------------
#define HB 16
__global__ __launch_bounds__(256)
void head_kernel(const float* __restrict__ mlp_w1,
                 const float* __restrict__ mlp_b1,
                 const float* __restrict__ mlp_w2,
                 const float* __restrict__ mlp_b2,
                 float* __restrict__ out)
{
    __shared__ float uis[HB * 128];
    __shared__ float red[32];
    __shared__ float res[HB];
    const int tid = threadIdx.x;
    const int b0 = blockIdx.x * HB;

    for (int i = tid; i < HB * 64; i += 256) {
        int bi = i >> 6, e = i & 63;
        uis[bi * 128 + e]      = g_ui[(b0 + bi) * EMB + e];
        uis[bi * 128 + 64 + e] = g_tv[(b0 + bi) * EMB + e];
    }
    __syncthreads();

    const int j = tid;
    float b1j = mlp_b1[j], w2j = mlp_w2[j], b2 = mlp_b2[0];
    for (int bi = 0; bi < HB; ++bi) {
        float acc = b1j;
        #pragma unroll 8
        for (int k = 0; k < 128; ++k)
            acc += uis[bi * 128 + k] * __ldg(&mlp_w1[k * HID + j]);
        float p = fmaxf(acc, 0.0f) * w2j;
        float s2 = block_reduce_sum(p, red, tid);
        if (tid == 0) res[bi] = s2;
    }
    __syncthreads();
    if (tid < HB) out[b0 + tid] = 1.0f / (1.0f + __expf(-(res[tid] + b2)));
}

extern "C" void kernel_launch(void* const* d_in, const int* in_sizes, int n_in,
                              void* d_out, int out_size) {
    const int*   user_hist   = (const int*)  d_in[0];
    const int*   target_item = (const int*)  d_in[1];
    const float* user_emb    = (const float*)d_in[2];
    const float* item_emb    = (const float*)d_in[3];
    const float* attn_w1     = (const float*)d_in[4];
    const float* attn_b1     = (const float*)d_in[5];
    const float* attn_w2     = (const float*)d_in[6];
    // d_in[7] = attn_b2 (constant shift inside softmax -> no effect)
    const float* mlp_w1      = (const float*)d_in[8];
    const float* mlp_b1      = (const float*)d_in[9];
    const float* mlp_w2      = (const float*)d_in[10];
    const float* mlp_b2      = (const float*)d_in[11];
    float* out = (float*)d_out;

    cudaFuncSetAttribute(din_kernel,
                         cudaFuncAttributeMaxDynamicSharedMemorySize, SMEM_BYTES);
    prep_kernel<<<EMB, 256>>>(attn_w1);
    din_kernel<<<BATCH, NT, SMEM_BYTES>>>(
        user_hist, target_item, user_emb, item_emb, attn_b1, attn_w2);
    head_kernel<<<BATCH / HB, 256>>>(mlp_w1, mlp_b1, mlp_w2, mlp_b2, out);
}

// round 11
// speedup vs baseline: 6.8147x; 1.3232x over previous
#include <cuda_runtime.h>
#include <cuda_bf16.h>
#include <cstdint>

// DIN forward via mma.sync bf16 tensor cores (compute_103-safe; no tcgen05).
// Algebra: att_in@W1 = h@Wb + bias,  Wb = (Wa+Wc) + t.*Wd  (per-batch, K=64),
//          bias tvec[j] = b1[j] + sum_e t[e]*(Wb_blk-Wc)[e][j].
// din_kernel (1 CTA/batch, 3 CTAs/SM): A=h bf16 [208x64], B=Wb bf16 [256n x 64k],
// warp mainloop: A frags for 2 m-tiles held in regs, one ldmatrix.x4 per
// (nt-pair, kk) feeds 4 MMAs. Epilogue fuses relu(.+tvec)*w2 into logits.
// head_kernel: k-outer MLP with f32x2 packed 16-batch accumulators.

#define BATCH 4096
#define SEQ   200
#define EMB   64
#define HID   256
#define NT    256

#define ASTR       72            // bf16 elems per row (64 + 8 pad)
#define ROWB       144           // bytes per row
#define MTILES     13
#define AROWS      208

typedef unsigned long long ull;

// ---- smem layout (bytes) ----
#define OFF_A      0
#define A_BYTES    (AROWS * ROWB)            // 29952
#define OFF_B      A_BYTES                   // [256 n][72 k] bf16
#define B_BYTES    (256 * ROWB)              // 36864
#define OFF_MISC   (OFF_B + B_BYTES)         // 66816
#define MO_HIST    0                         // int[200]
#define MO_TVAL    800                       // float[64]
#define MO_TW      1056                      // float2[256] {tvec, w2}
#define MO_LOGIT   3104                      // float[208]
#define MO_LOGW    3936                      // float[200]
#define MO_RED     4736                      // float[32]
#define MO_UIP     4864                      // float[512]
#define MISC_BYTES 6912
#define SMEM_BYTES (OFF_MISC + MISC_BYTES)   // 73728 -> 3 CTAs/SM

__device__ __nv_bfloat162 g_wacd[EMB * HID]; // {Wa+Wc, Wd}
__device__ __nv_bfloat16  g_diff[EMB * HID]; // Wb_blk - Wc
__device__ float g_ui[BATCH * EMB];
__device__ float g_tv[BATCH * EMB];

__device__ __forceinline__ uint32_t smem_to_u32(const void* p) {
    uint32_t a;
    asm("{ .reg .u64 t; cvta.to.shared.u64 t, %1; cvt.u32.u64 %0, t; }"
        : "=r"(a) : "l"(p));
    return a;
}
__device__ __forceinline__ ull pack4bf(float a, float b, float c, float d) {
    __nv_bfloat162 lo = __floats2bfloat162_rn(a, b);
    __nv_bfloat162 hi = __floats2bfloat162_rn(c, d);
    uint32_t l32 = *(uint32_t*)&lo, h32 = *(uint32_t*)&hi;
    ull r;
    asm("mov.b64 %0, {%1, %2};" : "=l"(r) : "r"(l32), "r"(h32));
    return r;
}
__device__ __forceinline__ void fma2(ull &d, ull a, ull b) {
    asm("fma.rn.f32x2 %0, %1, %2, %0;" : "+l"(d) : "l"(a), "l"(b));
}
__device__ __forceinline__ ull pk2(float x, float y) {
    ull r;
    asm("mov.b64 %0, {%1, %2};" : "=l"(r) : "f"(x), "f"(y));
    return r;
}
__device__ __forceinline__ float2 upk2(ull v) {
    float2 r;
    asm("mov.b64 {%0, %1}, %2;" : "=f"(r.x), "=f"(r.y) : "l"(v));
    return r;
}

#define LDSM_X4(r0, r1, r2, r3, addr) \
    asm volatile("ldmatrix.sync.aligned.m8n8.x4.shared.b16 {%0,%1,%2,%3}, [%4];" \
                 : "=r"(r0), "=r"(r1), "=r"(r2), "=r"(r3) : "r"(addr))
#define MMA16816(c0, c1, c2, c3, a0, a1, a2, a3, b0, b1) \
    asm volatile("mma.sync.aligned.m16n8k16.row.col.f32.bf16.bf16.f32 " \
                 "{%0,%1,%2,%3}, {%4,%5,%6,%7}, {%8,%9}, {%0,%1,%2,%3};" \
                 : "+f"(c0), "+f"(c1), "+f"(c2), "+f"(c3) \
                 : "r"(a0), "r"(a1), "r"(a2), "r"(a3), "r"(b0), "r"(b1))

__device__ __forceinline__ float block_reduce_sum(float v, float* red, int tid) {
    #pragma unroll
    for (int o = 16; o; o >>= 1) v += __shfl_xor_sync(0xffffffffu, v, o);
    if ((tid & 31) == 0) red[tid >> 5] = v;
    __syncthreads();
    if (tid < 32) {
        float r = (tid < 8) ? red[tid] : 0.0f;
        #pragma unroll
        for (int o = 4; o; o >>= 1) r += __shfl_xor_sync(0xffffffffu, r, o);
        if (tid == 0) red[0] = r;
    }
    __syncthreads();
    float out = red[0];
    __syncthreads();
    return out;
}
__device__ __forceinline__ float block_reduce_max(float v, float* red, int tid) {
    #pragma unroll
    for (int o = 16; o; o >>= 1) v = fmaxf(v, __shfl_xor_sync(0xffffffffu, v, o));
    if ((tid & 31) == 0) red[tid >> 5] = v;
    __syncthreads();
    if (tid < 32) {
        float r = (tid < 8) ? red[tid] : -3.4e38f;
        #pragma unroll
        for (int o = 4; o; o >>= 1) r = fmaxf(r, __shfl_xor_sync(0xffffffffu, r, o));
        if (tid == 0) red[0] = r;
    }
    __syncthreads();
    float out = red[0];
    __syncthreads();
    return out;
}

// ---------------- prep: static bf16 weight packs ----------------
__global__ void prep_kernel(const float* __restrict__ w1) {
    const int j = threadIdx.x;   // 0..255
    const int e = blockIdx.x;    // 0..63
    float wa = w1[e * HID + j];
    float wb = w1[(64 + e) * HID + j];
    float wc = w1[(128 + e) * HID + j];
    float wd = w1[(192 + e) * HID + j];
    g_wacd[e * HID + j] = __floats2bfloat162_rn(wa + wc, wd);
    g_diff[e * HID + j] = __float2bfloat16(wb - wc);
}

// ---------------- main: per-batch attention ----------------
__global__ __launch_bounds__(NT, 3)
void din_kernel(const int*   __restrict__ user_hist,
                const int*   __restrict__ target_item,
                const float* __restrict__ user_emb,
                const float* __restrict__ item_emb,
                const float* __restrict__ attn_b1,
                const float* __restrict__ attn_w2)
{
    extern __shared__ char smc[];
    const uint32_t smem_base = smem_to_u32(smc);
    const int tid = threadIdx.x, b = blockIdx.x;
    const int wid = tid >> 5, lane = tid & 31;

    char* miscc   = smc + OFF_MISC;
    int*    shist = (int*)(miscc + MO_HIST);
    float*  tvalS = (float*)(miscc + MO_TVAL);
    float2* twS   = (float2*)(miscc + MO_TW);
    float* logitS = (float*)(miscc + MO_LOGIT);
    float* logwS  = (float*)(miscc + MO_LOGW);
    float* redS   = (float*)(miscc + MO_RED);
    float* uipS   = (float*)(miscc + MO_UIP);

    // ---- phase 0: hist + target embedding ----
    if (tid < SEQ) shist[tid] = user_hist[b * SEQ + tid];
    if (tid < EMB) {
        int tgt = target_item[b];
        tvalS[tid] = item_emb[(size_t)tgt * EMB + tid];
    }
    __syncthreads();

    // ---- phase 1a: A = h bf16 [208 x 64], rows 200..207 zeroed ----
    {
        const float4* ue4 = (const float4*)user_emb;
        for (int u = tid; u < SEQ * 16; u += NT) {
            int s = u >> 4, q = u & 15;
            float4 h4 = ue4[(size_t)shist[s] * 16 + q];
            *(ull*)(smc + OFF_A + s * ROWB + q * 8) = pack4bf(h4.x, h4.y, h4.z, h4.w);
        }
        #pragma unroll
        for (int i = tid; i < 8 * ROWB / 4; i += NT)
            *(uint32_t*)(smc + OFF_A + SEQ * ROWB + i * 4) = 0;
    }

    // ---- phase 1b: B = Wb bf16 [256 n][64 k] + tvec ----
    {
        const int j = tid;
        float tv_acc = attn_b1[j];
        __nv_bfloat16* Brow = (__nv_bfloat16*)(smc + OFF_B + j * ROWB);
        #pragma unroll 8
        for (int e = 0; e < EMB; e += 2) {
            __nv_bfloat162 p0 = g_wacd[e * HID + j];
            __nv_bfloat162 p1 = g_wacd[(e + 1) * HID + j];
            float t0 = tvalS[e], t1 = tvalS[e + 1];
            float v0 = __bfloat162float(p0.x) + t0 * __bfloat162float(p0.y);
            float v1 = __bfloat162float(p1.x) + t1 * __bfloat162float(p1.y);
            *(__nv_bfloat162*)(Brow + e) = __floats2bfloat162_rn(v0, v1);
            tv_acc += t0 * __bfloat162float(g_diff[e * HID + j])
                    + t1 * __bfloat162float(g_diff[(e + 1) * HID + j]);
        }
        twS[j] = make_float2(tv_acc, attn_w2[j]);
    }
    __syncthreads();

    // ---- phase 2: GEMM [208x64]@[64x256] + fused relu*w2 logit epilogue ----
    {
        const uint32_t aBase = smem_base + OFF_A
                             + (uint32_t)(lane & 15) * ROWB + (uint32_t)(lane >> 4) * 16;
        // x4 B addressing: lanes 0-7 -> nt rows 0-7 k0-7, 8-15 -> k8-15,
        // 16-23 -> nt+1 rows k0-7, 24-31 -> nt+1 rows k8-15
        const uint32_t bBase = smem_base + OFF_B
                             + (uint32_t)(lane & 7) * ROWB + (uint32_t)((lane >> 3) & 1) * 16
                             + (uint32_t)(lane >> 4) * (8 * ROWB);
        const int mt0 = wid, mt1 = wid + 8;
        const bool two = (mt1 < MTILES);

        uint32_t a0[4][4], a1[4][4];
        #pragma unroll
        for (int kk = 0; kk < 4; ++kk)
            LDSM_X4(a0[kk][0], a0[kk][1], a0[kk][2], a0[kk][3],
                    aBase + (uint32_t)mt0 * (16 * ROWB) + (uint32_t)kk * 32);
        if (two) {
            #pragma unroll
            for (int kk = 0; kk < 4; ++kk)
                LDSM_X4(a1[kk][0], a1[kk][1], a1[kk][2], a1[kk][3],
                        aBase + (uint32_t)mt1 * (16 * ROWB) + (uint32_t)kk * 32);
        }

        float p0 = 0.f, p1 = 0.f, p2 = 0.f, p3 = 0.f;
        #pragma unroll 2
        for (int ntp = 0; ntp < 16; ++ntp) {
            float c[2][2][4];   // [nt-sub][tile][frag]
            #pragma unroll
            for (int q = 0; q < 2; ++q)
                #pragma unroll
                for (int t = 0; t < 2; ++t)
                    #pragma unroll
                    for (int f = 0; f < 4; ++f) c[q][t][f] = 0.f;

            #pragma unroll
            for (int kk = 0; kk < 4; ++kk) {
                uint32_t b0, b1, b2, b3;
                LDSM_X4(b0, b1, b2, b3,
                        bBase + (uint32_t)ntp * (16 * ROWB) + (uint32_t)kk * 32);
                MMA16816(c[0][0][0], c[0][0][1], c[0][0][2], c[0][0][3],
                         a0[kk][0], a0[kk][1], a0[kk][2], a0[kk][3], b0, b1);
                MMA16816(c[1][0][0], c[1][0][1], c[1][0][2], c[1][0][3],
                         a0[kk][0], a0[kk][1], a0[kk][2], a0[kk][3], b2, b3);
                if (two) {
                    MMA16816(c[0][1][0], c[0][1][1], c[0][1][2], c[0][1][3],
                             a1[kk][0], a1[kk][1], a1[kk][2], a1[kk][3], b0, b1);
                    MMA16816(c[1][1][0], c[1][1][1], c[1][1][2], c[1][1][3],
                             a1[kk][0], a1[kk][1], a1[kk][2], a1[kk][3], b2, b3);
                }
            }
            #pragma unroll
            for (int q = 0; q < 2; ++q) {
                int nt = ntp * 2 + q;
                float4 tw = *(const float4*)(twS + (nt * 8 + (lane & 3) * 2));
                p0 += fmaxf(c[q][0][0] + tw.x, 0.f) * tw.y
                    + fmaxf(c[q][0][1] + tw.z, 0.f) * tw.w;
                p1 += fmaxf(c[q][0][2] + tw.x, 0.f) * tw.y
                    + fmaxf(c[q][0][3] + tw.z, 0.f) * tw.w;
                if (two) {
                    p2 += fmaxf(c[q][1][0] + tw.x, 0.f) * tw.y
                        + fmaxf(c[q][1][1] + tw.z, 0.f) * tw.w;
                    p3 += fmaxf(c[q][1][2] + tw.x, 0.f) * tw.y
                        + fmaxf(c[q][1][3] + tw.z, 0.f) * tw.w;
                }
            }
        }
        p0 += __shfl_xor_sync(0xffffffffu, p0, 1);
        p0 += __shfl_xor_sync(0xffffffffu, p0, 2);
        p1 += __shfl_xor_sync(0xffffffffu, p1, 1);
        p1 += __shfl_xor_sync(0xffffffffu, p1, 2);
        p2 += __shfl_xor_sync(0xffffffffu, p2, 1);
        p2 += __shfl_xor_sync(0xffffffffu, p2, 2);
        p3 += __shfl_xor_sync(0xffffffffu, p3, 1);
        p3 += __shfl_xor_sync(0xffffffffu, p3, 2);
        if ((lane & 3) == 0) {
            int r = mt0 * 16 + (lane >> 2);
            logitS[r] = p0;
            logitS[r + 8] = p1;
            if (two) {
                int r2 = mt1 * 16 + (lane >> 2);
                logitS[r2] = p2;
                logitS[r2 + 8] = p3;
            }
        }
    }
    __syncthreads();

    // ---- phase 3: softmax over S ----
    {
        float l = -3.4e38f;
        if (tid < SEQ) l = logitS[tid];
        float mx = block_reduce_max(l, redS, tid);
        float ex = (tid < SEQ) ? __expf(l - mx) : 0.0f;
        float sm = block_reduce_sum(ex, redS, tid);
        if (tid < SEQ) logwS[tid] = ex / sm;
    }
    __syncthreads();

    // ---- phase 4: user_interest from bf16 A tile (vectorized) ----
    {
        int ep = lane;            // e-pair 0..31
        int part = tid >> 5;      // 8 parts x 25 s
        float ax = 0.f, ay = 0.f;
        int sA = part * 25;
        #pragma unroll 5
        for (int s = sA; s < sA + 25; ++s) {
            float w = logwS[s];
            __nv_bfloat162 hv = *(const __nv_bfloat162*)(smc + OFF_A + s * ROWB + ep * 4);
            float2 f = __bfloat1622float2(hv);
            ax += w * f.x;
            ay += w * f.y;
        }
        uipS[part * 64 + ep * 2]     = ax;
        uipS[part * 64 + ep * 2 + 1] = ay;
    }
    __syncthreads();
    if (tid < EMB) {
        float ui = 0.f;
        #pragma unroll
        for (int p = 0; p < 8; ++p) ui += uipS[p * 64 + tid];
        g_ui[b * EMB + tid] = ui;
        g_tv[b * EMB + tid] = tvalS[tid];
    }
}

// ---------------- head: prediction MLP, 16 batches per CTA, k-outer ----------------
#define HB 16
#define USTR 18   // float stride per k row (16 bi + 2 pad)
__global__ __launch_bounds__(256)
void head_kernel(const float* __restrict__ mlp_w1,
                 const float* __restrict__ mlp_b1,
                 const float* __restrict__ mlp_w2,
                 const float* __restrict__ mlp_b2,
                 float* __restrict__ out)
{
    __shared__ float uis2[128 * USTR];   // [k][bi]
    __shared__ float redM[HB * 8];
    const int tid = threadIdx.x;
    const int wid = tid >> 5, lane = tid & 31;
    const int b0 = blockIdx.x * HB;

    for (int i = tid; i < HB * 64; i += 256) {
        int bi = i >> 6, e = i & 63;     // coalesced global reads
        uis2[e * USTR + bi]        = g_ui[(b0 + bi) * EMB + e];
        uis2[(64 + e) * USTR + bi] = g_tv[(b0 + bi) * EMB + e];
    }
    __syncthreads();

    const int j = tid;
    float b1j = mlp_b1[j], w2j = mlp_w2[j], b2 = mlp_b2[0];
    ull acc2[8];
    ull binit = pk2(b1j, b1j);
    #pragma unroll
    for (int p = 0; p < 8; ++p) acc2[p] = (p == 0) ? binit : pk2(0.f, 0.f);

    #pragma unroll 4
    for (int k = 0; k < 128; ++k) {
        float w = __ldg(&mlp_w1[k * HID + j]);
        ull wv = pk2(w, w);
        const ull* up = (const ull*)(uis2 + k * USTR);
        #pragma unroll
        for (int p = 0; p < 8; ++p) fma2(acc2[p], up[p], wv);
    }

    // unpack, relu*w2, reduce over j (256 threads) per bi
    float av[HB];
    #pragma unroll
    for (int p = 0; p < 8; ++p) {
        float2 v = upk2(acc2[p]);
        av[2 * p] = v.x;
        av[2 * p + 1] = v.y;
    }
    // acc2[0] carried the bias for bi pair {0,1} only; add bias for the rest
    #pragma unroll
    for (int bi = 2; bi < HB; ++bi) av[bi] += b1j;

    #pragma unroll
    for (int bi = 0; bi < HB; ++bi) {
        float v = fmaxf(av[bi], 0.f) * w2j;
        #pragma unroll
        for (int o = 16; o; o >>= 1) v += __shfl_xor_sync(0xffffffffu, v, o);
        if (lane == 0) redM[bi * 8 + wid] = v;
    }
    __syncthreads();
    if (tid < HB) {
        float s = 0.f;
        #pragma unroll
        for (int w = 0; w < 8; ++w) s += redM[tid * 8 + w];
        out[b0 + tid] = 1.0f / (1.0f + __expf(-(s + b2)));
    }
}

extern "C" void kernel_launch(void* const* d_in, const int* in_sizes, int n_in,
                              void* d_out, int out_size) {
    const int*   user_hist   = (const int*)  d_in[0];
    const int*   target_item = (const int*)  d_in[1];
    const float* user_emb    = (const float*)d_in[2];
    const float* item_emb    = (const float*)d_in[3];
    const float* attn_w1     = (const float*)d_in[4];
    const float* attn_b1     = (const float*)d_in[5];
    const float* attn_w2     = (const float*)d_in[6];
    // d_in[7] = attn_b2 (constant shift inside softmax -> no effect)
    const float* mlp_w1      = (const float*)d_in[8];
    const float* mlp_b1      = (const float*)d_in[9];
    const float* mlp_w2      = (const float*)d_in[10];
    const float* mlp_b2      = (const float*)d_in[11];
    float* out = (float*)d_out;

    cudaFuncSetAttribute(din_kernel,
                         cudaFuncAttributeMaxDynamicSharedMemorySize, SMEM_BYTES);
    prep_kernel<<<EMB, 256>>>(attn_w1);
    din_kernel<<<BATCH, NT, SMEM_BYTES>>>(
        user_hist, target_item, user_emb, item_emb, attn_b1, attn_w2);
    head_kernel<<<BATCH / HB, 256>>>(mlp_w1, mlp_b1, mlp_w2, mlp_b2, out);
}